// round 10
// baseline (speedup 1.0000x reference)
#include <cuda_runtime.h>
#include <cuda_fp16.h>
#include <cstdint>

// ---------------------------------------------------------------------------
// Problem constants
// ---------------------------------------------------------------------------
#define M_TOT 512
#define N_TOT 11008
#define K_TOT 4096
#define KGROUPS (K_TOT / 32)              // 128 groups along K per output feature
#define NGROUPS (N_TOT * KGROUPS)         // 1,409,024 total groups

// GEMM tiling: CTA 128x128x64; 4 MMA warps (2x2 of 64x64) + 4 producer warps
#define BM 128
#define BN 128
#define BK 64                              // 64 fp16 = 128B rows (SW128 atom)
#define NTILES (K_TOT / BK)                // 64
#define NTHREADS 256
#define NSTAGES 4
#define STAGE_BYTES 32768                  // A 16KB + B 16KB
#define B_OFF 16384
#define CTRL_OFF (NSTAGES * STAGE_BYTES)   // 131072
#define OFF_FULL(s) (CTRL_OFF + (s) * 8)
#define OFF_FREE(s) (CTRL_OFF + 32 + (s) * 8)
#define SMEM_BYTES (CTRL_OFF + 64)

// Scratch (device globals: no allocation allowed)
__device__ __half g_xh[M_TOT * K_TOT];     // 4 MB   x in fp16
__device__ uint4  g_wpack[NGROUPS];        // 22.5 MB, k-block-major: [kb][n]
__device__ int    g_nmode;                 // 0=f32, 1=f16, 2=bf16

// ---------------------------------------------------------------------------
// helpers
// ---------------------------------------------------------------------------
__device__ __forceinline__ uint32_t smem_to_u32(const void* p) {
    uint32_t a;
    asm("{ .reg .u64 t; cvta.to.shared.u64 t, %1; cvt.u32.u64 %0, t; }" : "=r"(a) : "l"(p));
    return a;
}
__device__ __forceinline__ uint32_t sw128(uint32_t off) {
    return off ^ ((off >> 3) & 0x70);
}
#define CP_ASYNC16(dst, src) \
    asm volatile("cp.async.cg.shared.global [%0], [%1], 16;" :: "r"(dst), "l"(src) : "memory")
#define CP_MBAR_ARRIVE(mbar) \
    asm volatile("cp.async.mbarrier.arrive.shared::cta.b64 [%0];" :: "r"((uint32_t)(mbar)) : "memory")

#define MBARRIER_INIT(addr, cnt) \
    asm volatile("mbarrier.init.shared.b64 [%0], %1;" :: "r"((uint32_t)(addr)), "r"((uint32_t)(cnt)) : "memory")
#define MBARRIER_ARRIVE(addr) \
    asm volatile("mbarrier.arrive.release.cta.shared::cta.b64 _, [%0];" :: "r"((uint32_t)(addr)) : "memory")
#define MBARRIER_WAIT_PARITY(addr, par) do {                                   \
    uint32_t _m = (uint32_t)(addr);                                            \
    uint32_t _p = (uint32_t)(par);                                             \
    asm volatile(                                                              \
        "{\n\t.reg .pred P1;\n\t"                                              \
        "WAIT_LP_%=:\n\t"                                                      \
        "mbarrier.try_wait.parity.acquire.cta.shared::cta.b64 P1, [%0], %1, 0x989680;\n\t" \
        "@P1 bra.uni WAIT_DN_%=;\n\t"                                          \
        "bra.uni WAIT_LP_%=;\n\t"                                              \
        "WAIT_DN_%=:\n\t}"                                                     \
        :: "r"(_m), "r"(_p) : "memory");                                       \
} while (0)

#define LDMATRIX_X4(r0, r1, r2, r3, addr) \
    asm volatile("ldmatrix.sync.aligned.m8n8.x4.shared.b16 {%0,%1,%2,%3}, [%4];" \
                 : "=r"(r0), "=r"(r1), "=r"(r2), "=r"(r3) : "r"(addr))

// ---------------------------------------------------------------------------
// P0: sniff weight_norm marshaled dtype (bf16 checked first — see R5 analysis)
// ---------------------------------------------------------------------------
__global__ void k_sniff(const void* __restrict__ norm) {
    const uint16_t* p16 = (const uint16_t*)norm;
    const float*    p32 = (const float*)norm;
    bool bf_ok = true, f32_ok = true;
    for (int i = 0; i < 16; ++i) {
        float fb = __uint_as_float(((uint32_t)p16[i]) << 16);
        if (!(fb > 0.005f && fb < 0.2f)) bf_ok = false;
        float ff = p32[i];
        if (!(ff > 0.005f && ff < 0.2f)) f32_ok = false;
    }
    g_nmode = bf_ok ? 2 : (f32_ok ? 0 : 1);
}

// ---------------------------------------------------------------------------
// P1: x fp32 -> fp16
// ---------------------------------------------------------------------------
__global__ void k_cvt_x(const float* __restrict__ x) {
    int i = blockIdx.x * blockDim.x + threadIdx.x;
    float4 v = reinterpret_cast<const float4*>(x)[i];
    __half2* dst = reinterpret_cast<__half2*>(g_xh) + 2 * i;
    dst[0] = __floats2half2_rn(v.x, v.y);
    dst[1] = __floats2half2_rn(v.z, v.w);
}

// ---------------------------------------------------------------------------
// P2: repack 3-bit codes into 16B/group records, k-block-major for coalescing
// ---------------------------------------------------------------------------
__global__ void k_repack(const int* __restrict__ q3, const void* __restrict__ norm) {
    int g = blockIdx.x * blockDim.x + threadIdx.x;     // input group: n-major
    const int4* p = reinterpret_cast<const int4*>(q3) + g * 3;
    int4 c0 = p[0], c1 = p[1], c2 = p[2];
    uint4 o;
    o.x = (uint32_t)(c0.x & 255) | ((uint32_t)(c0.y & 255) << 8) |
          ((uint32_t)(c0.z & 255) << 16) | ((uint32_t)(c0.w & 255) << 24);
    o.y = (uint32_t)(c1.x & 255) | ((uint32_t)(c1.y & 255) << 8) |
          ((uint32_t)(c1.z & 255) << 16) | ((uint32_t)(c1.w & 255) << 24);
    o.z = (uint32_t)(c2.x & 255) | ((uint32_t)(c2.y & 255) << 8) |
          ((uint32_t)(c2.z & 255) << 16) | ((uint32_t)(c2.w & 255) << 24);
    const int mode = g_nmode;
    float nf;
    if (mode == 0)      nf = ((const float*)norm)[g];
    else if (mode == 1) nf = __half2float(((const __half*)norm)[g]);
    else                nf = __uint_as_float(((uint32_t)((const uint16_t*)norm)[g]) << 16);
    o.w = __float_as_uint(nf);
    const int n  = g / KGROUPS;          // 0..N_TOT-1
    const int kb = g % KGROUPS;          // 0..127
    g_wpack[(size_t)kb * N_TOT + n] = o; // k-block-major
}

// ---------------------------------------------------------------------------
// Fused dequant + GEMM, warp-specialized:
//   warps 0-3: MMA consumers (64x64 tiles), warps 4-7: producers
//   4-stage mbarrier ring; cp.async A folded into full[] via cp.async.mbarrier
// ---------------------------------------------------------------------------
__global__ void __launch_bounds__(NTHREADS, 1)
k_gemm(const float* __restrict__ bias, float* __restrict__ out) {
    extern __shared__ char smem[];
    const uint32_t sb = smem_to_u32(smem);

    const int tid  = threadIdx.x;
    const int lane = tid & 31;
    const int warp = tid >> 5;
    const int n_base = blockIdx.x * BN;
    const int m_base = blockIdx.y * BM;

    if (tid == 0) {
#pragma unroll
        for (int s = 0; s < NSTAGES; ++s) {
            MBARRIER_INIT(sb + OFF_FULL(s), 128);   // producer dequant arrives
            MBARRIER_INIT(sb + OFF_FREE(s), 128);   // consumer arrives
        }
    }
    __syncthreads();

    if (warp < 4) {
        // =================== CONSUMER: pure ldmatrix + mma ===================
        const int wm = warp >> 1;          // 0..1 (64 rows)
        const int wn = warp & 1;           // 0..1 (64 cols)
        const uint32_t a_lane = (uint32_t)(wm * 8192 + (lane & 15) * 128 + (lane >> 4) * 16);
        const uint32_t b_lane = (uint32_t)(wn * 8192 + (((lane >> 4) << 3) + (lane & 7)) * 128 +
                                           ((lane >> 3) & 1) * 16);
        float acc[4][8][4];
#pragma unroll
        for (int mi = 0; mi < 4; ++mi)
#pragma unroll
            for (int ni = 0; ni < 8; ++ni)
#pragma unroll
                for (int c = 0; c < 4; ++c) acc[mi][ni][c] = 0.0f;

#pragma unroll 1
        for (int t = 0; t < NTILES; ++t) {
            const int s  = t & (NSTAGES - 1);
            const int ph = (t >> 2) & 1;
            MBARRIER_WAIT_PARITY(sb + OFF_FULL(s), ph);
            const uint32_t Ab = sb + s * STAGE_BYTES;
            const uint32_t Bb = Ab + B_OFF;
#pragma unroll
            for (int ks = 0; ks < 4; ++ks) {
                uint32_t a[4][4], b[8][2];
#pragma unroll
                for (int mi = 0; mi < 4; ++mi)
                    LDMATRIX_X4(a[mi][0], a[mi][1], a[mi][2], a[mi][3],
                                Ab + sw128(a_lane + mi * 2048 + ks * 32));
#pragma unroll
                for (int nj = 0; nj < 4; ++nj)
                    LDMATRIX_X4(b[2 * nj][0], b[2 * nj][1], b[2 * nj + 1][0], b[2 * nj + 1][1],
                                Bb + sw128(b_lane + nj * 2048 + ks * 32));
#pragma unroll
                for (int mi = 0; mi < 4; ++mi)
#pragma unroll
                    for (int ni = 0; ni < 8; ++ni)
                        asm volatile(
                            "mma.sync.aligned.m16n8k16.row.col.f32.f16.f16.f32 "
                            "{%0,%1,%2,%3}, {%4,%5,%6,%7}, {%8,%9}, {%0,%1,%2,%3};\n"
                            : "+f"(acc[mi][ni][0]), "+f"(acc[mi][ni][1]),
                              "+f"(acc[mi][ni][2]), "+f"(acc[mi][ni][3])
                            : "r"(a[mi][0]), "r"(a[mi][1]), "r"(a[mi][2]), "r"(a[mi][3]),
                              "r"(b[ni][0]), "r"(b[ni][1]));
            }
            MBARRIER_ARRIVE(sb + OFF_FREE(s));
        }

        // epilogue: add bias, write fp32
#pragma unroll
        for (int mi = 0; mi < 4; ++mi) {
            const int r0 = m_base + wm * 64 + mi * 16 + (lane >> 2);
#pragma unroll
            for (int ni = 0; ni < 8; ++ni) {
                const int col = n_base + wn * 64 + ni * 8 + (lane & 3) * 2;
                float2 bb = *reinterpret_cast<const float2*>(bias + col);
                float2 v0 = make_float2(acc[mi][ni][0] + bb.x, acc[mi][ni][1] + bb.y);
                float2 v1 = make_float2(acc[mi][ni][2] + bb.x, acc[mi][ni][3] + bb.y);
                *reinterpret_cast<float2*>(out + (size_t)r0 * N_TOT + col) = v0;
                *reinterpret_cast<float2*>(out + (size_t)(r0 + 8) * N_TOT + col) = v1;
            }
        }
    } else {
        // =================== PRODUCER: cp.async A + dequant B ===================
        const int ptid = tid - 128;        // 0..127
        uint4 breg[2][2];

        auto ldg_B = [&](int t) {
            const size_t base = (size_t)(t * 2) * N_TOT + n_base + ptid;
            breg[t & 1][0] = g_wpack[base];
            breg[t & 1][1] = g_wpack[base + N_TOT];
        };

        uint32_t c1024u = 0x64006400u;
        const __half2 h1024 = *reinterpret_cast<const __half2*>(&c1024u);

        ldg_B(0);

#pragma unroll 1
        for (int t = 0; t < NTILES; ++t) {
            const int s   = t & (NSTAGES - 1);
            const int php = 1 ^ ((t >> 2) & 1);
            MBARRIER_WAIT_PARITY(sb + OFF_FREE(s), php);

            // ---- A tile via cp.async (8 x 16B per producer thread)
            {
                const uint32_t dbase = sb + s * STAGE_BYTES;
                const __half* src0 = g_xh + (size_t)m_base * K_TOT + t * BK;
#pragma unroll
                for (int i = 0; i < 8; ++i) {
                    int id = i * 128 + ptid;          // 0..1023
                    int row = id >> 3, c8 = id & 7;
                    uint32_t dst = dbase + sw128((uint32_t)(row * 128 + c8 * 16));
                    CP_ASYNC16(dst, src0 + (size_t)row * K_TOT + c8 * 8);
                }
                CP_MBAR_ARRIVE(sb + OFF_FULL(s));   // arrives when A lands
            }

            if (t + 1 < NTILES) ldg_B(t + 1);       // prefetch next weights

            // ---- B tile: dequant 2 groups (64 values), half2 path
            {
                char* Bb = smem + s * STAGE_BYTES + B_OFF;
                const uint4* br = breg[t & 1];
#pragma unroll
                for (int gk = 0; gk < 2; ++gk) {
                    const uint4 r = br[gk];
                    float nf = __uint_as_float(r.w);
                    float sc = nf * (1.0f / 7.0f);
                    const __half2 h2s = __float2half2_rn(2.0f * sc);
                    const __half2 hm7 = __float2half2_rn(-7.0f * sc);
                    uint32_t tt[4];
                    tt[0] = r.x & 0x00FFFFFFu;
                    tt[1] = (r.x >> 24) | ((r.y & 0x0000FFFFu) << 8);
                    tt[2] = (r.y >> 16) | ((r.z & 0x000000FFu) << 16);
                    tt[3] = (r.z >> 8);
                    const uint32_t base = (uint32_t)(ptid * 128 + gk * 64);
#pragma unroll
                    for (int j = 0; j < 4; ++j) {
                        const uint32_t c = tt[j];
                        uint32_t pk[4];
#pragma unroll
                        for (int i = 0; i < 4; ++i) {
                            uint32_t tv = c >> (6 * i);
                            // (1024+q_lo, 1024+q_hi) exactly via fp16 mantissa trick
                            uint32_t rr = ((tv & 7u) | ((tv & 0x38u) << 13)) | 0x64006400u;
                            __half2 h = *reinterpret_cast<__half2*>(&rr);
                            __half2 q = __hsub2(h, h1024);        // exact
                            __half2 w = __hfma2(q, h2s, hm7);     // s*(2q-7)
                            pk[i] = *reinterpret_cast<uint32_t*>(&w);
                        }
                        uint4 v = make_uint4(pk[0], pk[1], pk[2], pk[3]);
                        *reinterpret_cast<uint4*>(Bb + sw128(base + j * 16)) = v;
                    }
                }
            }
            MBARRIER_ARRIVE(sb + OFF_FULL(s));
        }
    }
}

// ---------------------------------------------------------------------------
// Launch
// ---------------------------------------------------------------------------
extern "C" void kernel_launch(void* const* d_in, const int* in_sizes, int n_in,
                              void* d_out, int out_size) {
    const float* x    = (const float*)d_in[0];
    const int*   q3   = (const int*)d_in[1];
    const void*  norm = (const void*)d_in[2];
    const float* bias = (const float*)d_in[3];
    float*       out  = (float*)d_out;

    k_sniff<<<1, 1>>>(norm);
    k_cvt_x<<<(M_TOT * K_TOT / 4) / 256, 256>>>(x);
    k_repack<<<NGROUPS / 256, 256>>>(q3, norm);

    cudaFuncSetAttribute((const void*)k_gemm,
                         cudaFuncAttributeMaxDynamicSharedMemorySize, SMEM_BYTES);
    dim3 grid(N_TOT / BN, M_TOT / BM);   // 86 x 4
    k_gemm<<<grid, NTHREADS, SMEM_BYTES>>>(bias, out);
}

// round 11
// speedup vs baseline: 1.2669x; 1.2669x over previous
#include <cuda_runtime.h>
#include <cuda_fp16.h>
#include <cstdint>

// ---------------------------------------------------------------------------
// Problem constants
// ---------------------------------------------------------------------------
#define M_TOT 512
#define N_TOT 11008
#define K_TOT 4096
#define KGROUPS (K_TOT / 32)              // 128 groups along K per output feature
#define NGROUPS (N_TOT * KGROUPS)         // 1,409,024 total groups

// GEMM tiling: CTA 128x64x64; 4 warps in 2x2 grid of 64x32 warp tiles
#define BM 128
#define BN 64
#define BK 64                              // 64 fp16 = 128B rows (SW128 atom)
#define NTILES (K_TOT / BK)                // 64
#define NTHREADS 128
#define STAGE_BYTES 24576                  // A 16KB + B 8KB
#define B_OFF 16384
#define SMEM_BYTES (2 * STAGE_BYTES)       // 48 KB (double buffer) -> 3 CTAs/SM

#define NREPACK_BLOCKS (NGROUPS / 256)     // 5504
#define NCVT_BLOCKS ((M_TOT * K_TOT / 4) / 256)  // 2048

// Scratch (device globals: no allocation allowed)
__device__ __half g_xh[M_TOT * K_TOT];     // 4 MB   x in fp16
__device__ uint4  g_wpack[NGROUPS];        // 22.5 MB, k-block-major: [kb][n]

// ---------------------------------------------------------------------------
// helpers
// ---------------------------------------------------------------------------
__device__ __forceinline__ uint32_t smem_to_u32(const void* p) {
    uint32_t a;
    asm("{ .reg .u64 t; cvta.to.shared.u64 t, %1; cvt.u32.u64 %0, t; }" : "=r"(a) : "l"(p));
    return a;
}
__device__ __forceinline__ uint32_t sw128(uint32_t off) {
    return off ^ ((off >> 3) & 0x70);
}
__device__ __forceinline__ uint32_t pack_h2(float a, float b) {
    __half2 h = __floats2half2_rn(a, b);
    return *reinterpret_cast<uint32_t*>(&h);
}
#define CP_ASYNC16(dst, src) \
    asm volatile("cp.async.cg.shared.global [%0], [%1], 16;" :: "r"(dst), "l"(src) : "memory")
#define CP_COMMIT() asm volatile("cp.async.commit_group;" ::: "memory")
#define CP_WAIT0()  asm volatile("cp.async.wait_group 0;" ::: "memory")

#define LDMATRIX_X4(r0, r1, r2, r3, addr) \
    asm volatile("ldmatrix.sync.aligned.m8n8.x4.shared.b16 {%0,%1,%2,%3}, [%4];" \
                 : "=r"(r0), "=r"(r1), "=r"(r2), "=r"(r3) : "r"(addr))

// ---------------------------------------------------------------------------
// P1 (single launch): repack weights (+inline norm-dtype sniff) AND x->fp16.
// Blocks [0, NREPACK_BLOCKS) repack; blocks [NREPACK_BLOCKS, +NCVT_BLOCKS) cvt.
// ---------------------------------------------------------------------------
__global__ void k_prep(const float* __restrict__ x,
                       const int* __restrict__ q3,
                       const void* __restrict__ norm) {
    const int blk = blockIdx.x;
    if (blk < NREPACK_BLOCKS) {
        // ---- inline dtype sniff (norms are in (0.01,0.11) by construction).
        // bf16 must be tested before f32: an f32-read of a bf16 buffer aliases
        // into range, the converse has negligible probability. Same-address
        // loads across all threads -> L1 broadcast, effectively free.
        const uint16_t* p16 = (const uint16_t*)norm;
        const float*    p32 = (const float*)norm;
        bool bf_ok = true, f32_ok = true;
#pragma unroll
        for (int i = 0; i < 16; ++i) {
            float fb = __uint_as_float(((uint32_t)p16[i]) << 16);
            if (!(fb > 0.005f && fb < 0.2f)) bf_ok = false;
        }
#pragma unroll
        for (int i = 0; i < 8; ++i) {
            float ff = p32[i];
            if (!(ff > 0.005f && ff < 0.2f)) f32_ok = false;
        }
        const int mode = bf_ok ? 2 : (f32_ok ? 0 : 1);   // 2=bf16,0=f32,1=f16

        int g = blk * 256 + threadIdx.x;                 // input group: n-major
        const int4* p = reinterpret_cast<const int4*>(q3) + g * 3;
        int4 c0 = p[0], c1 = p[1], c2 = p[2];
        uint4 o;
        o.x = (uint32_t)(c0.x & 255) | ((uint32_t)(c0.y & 255) << 8) |
              ((uint32_t)(c0.z & 255) << 16) | ((uint32_t)(c0.w & 255) << 24);
        o.y = (uint32_t)(c1.x & 255) | ((uint32_t)(c1.y & 255) << 8) |
              ((uint32_t)(c1.z & 255) << 16) | ((uint32_t)(c1.w & 255) << 24);
        o.z = (uint32_t)(c2.x & 255) | ((uint32_t)(c2.y & 255) << 8) |
              ((uint32_t)(c2.z & 255) << 16) | ((uint32_t)(c2.w & 255) << 24);
        float nf;
        if (mode == 0)      nf = p32[g];
        else if (mode == 1) nf = __half2float(((const __half*)norm)[g]);
        else                nf = __uint_as_float(((uint32_t)p16[g]) << 16);
        o.w = __float_as_uint(nf);
        const int n  = g / KGROUPS;          // 0..N_TOT-1
        const int kb = g % KGROUPS;          // 0..127
        g_wpack[(size_t)kb * N_TOT + n] = o; // k-block-major for coalescing
    } else {
        int i = (blk - NREPACK_BLOCKS) * 256 + threadIdx.x;   // one float4
        float4 v = reinterpret_cast<const float4*>(x)[i];
        __half2* dst = reinterpret_cast<__half2*>(g_xh) + 2 * i;
        dst[0] = __floats2half2_rn(v.x, v.y);
        dst[1] = __floats2half2_rn(v.z, v.w);
    }
}

// ---------------------------------------------------------------------------
// Fused dequant + GEMM: CTA 128x64, 4 warps (64x32 tiles), cp.async A,
// ldmatrix frags, double buffer, 3 CTAs/SM for tail smoothing.
// ---------------------------------------------------------------------------
__global__ void __launch_bounds__(NTHREADS, 3)
k_gemm(const float* __restrict__ bias, float* __restrict__ out) {
    extern __shared__ char smem[];
    const uint32_t sb = smem_to_u32(smem);

    const int tid  = threadIdx.x;
    const int lane = tid & 31;
    const int warp = tid >> 5;
    const int wm   = warp >> 1;           // 0..1 (64 rows)
    const int wn   = warp & 1;            // 0..1 (32 cols)
    const int n_base = blockIdx.x * BN;
    const int m_base = blockIdx.y * BM;

    // lane-constant fragment address components (bytes within tile)
    const uint32_t a_lane = (uint32_t)(wm * 8192 + (lane & 15) * 128 + (lane >> 4) * 16);
    const uint32_t b_lane = (uint32_t)(wn * 4096 + (((lane >> 4) << 3) + (lane & 7)) * 128 +
                                       ((lane >> 3) & 1) * 16);

    float acc[4][4][4];
#pragma unroll
    for (int mi = 0; mi < 4; ++mi)
#pragma unroll
        for (int ni = 0; ni < 4; ++ni)
#pragma unroll
            for (int c = 0; c < 4; ++c) acc[mi][ni][c] = 0.0f;

    // per-thread B record: feature row = tid>>1, k-group = tid&1
    const int b_n  = tid >> 1;
    const int b_gk = tid & 1;
    uint4 breg;

    auto cpasync_A = [&](int t, int buf) {
        const uint32_t dbase = sb + buf * STAGE_BYTES;
        const __half* src0 = g_xh + (size_t)m_base * K_TOT + t * BK;
#pragma unroll
        for (int i = 0; i < 8; ++i) {
            int id = i * NTHREADS + tid;          // 0..1023
            int row = id >> 3, c8 = id & 7;
            uint32_t dst = dbase + sw128((uint32_t)(row * 128 + c8 * 16));
            CP_ASYNC16(dst, src0 + (size_t)row * K_TOT + c8 * 8);
        }
        CP_COMMIT();
    };

    auto ldg_B = [&](int t) {
        breg = g_wpack[(size_t)(t * 2 + b_gk) * N_TOT + n_base + b_n];
    };

    // dequant 1 group (32 values) -> 4 swizzled 16B stores
    auto store_B = [&](int buf) {
        char* Bb = smem + buf * STAGE_BYTES + B_OFF;
        const uint4 r = breg;
        float nf    = __uint_as_float(r.w);
        float s     = nf * (1.0f / 7.0f);
        float two_s = s + s;
        float m7s   = -7.0f * s;
        uint32_t tt[4];
        tt[0] = r.x & 0x00FFFFFFu;
        tt[1] = (r.x >> 24) | ((r.y & 0x0000FFFFu) << 8);
        tt[2] = (r.y >> 16) | ((r.z & 0x000000FFu) << 16);
        tt[3] = (r.z >> 8);
        const uint32_t base = (uint32_t)(b_n * 128 + b_gk * 64);
#pragma unroll
        for (int j = 0; j < 4; ++j) {
            const uint32_t c = tt[j];
            float f[8];
#pragma unroll
            for (int i = 0; i < 8; ++i) {
                float fv = __uint_as_float(((c >> (3 * i)) & 7u) | 0x4B000000u) - 8388608.0f;
                f[i] = fmaf(fv, two_s, m7s);   // s*(2q-7)
            }
            uint4 pk;
            pk.x = pack_h2(f[0], f[1]);
            pk.y = pack_h2(f[2], f[3]);
            pk.z = pack_h2(f[4], f[5]);
            pk.w = pack_h2(f[6], f[7]);
            *reinterpret_cast<uint4*>(Bb + sw128(base + j * 16)) = pk;
        }
    };

    auto compute = [&](int buf) {
        const uint32_t Ab = sb + buf * STAGE_BYTES;
        const uint32_t Bb = Ab + B_OFF;
#pragma unroll
        for (int ks = 0; ks < 4; ++ks) {
            uint32_t a[4][4], b[4][2];
#pragma unroll
            for (int mi = 0; mi < 4; ++mi)
                LDMATRIX_X4(a[mi][0], a[mi][1], a[mi][2], a[mi][3],
                            Ab + sw128(a_lane + mi * 2048 + ks * 32));
#pragma unroll
            for (int nj = 0; nj < 2; ++nj)
                LDMATRIX_X4(b[2 * nj][0], b[2 * nj][1], b[2 * nj + 1][0], b[2 * nj + 1][1],
                            Bb + sw128(b_lane + nj * 2048 + ks * 32));
#pragma unroll
            for (int mi = 0; mi < 4; ++mi)
#pragma unroll
                for (int ni = 0; ni < 4; ++ni)
                    asm volatile(
                        "mma.sync.aligned.m16n8k16.row.col.f32.f16.f16.f32 "
                        "{%0,%1,%2,%3}, {%4,%5,%6,%7}, {%8,%9}, {%0,%1,%2,%3};\n"
                        : "+f"(acc[mi][ni][0]), "+f"(acc[mi][ni][1]),
                          "+f"(acc[mi][ni][2]), "+f"(acc[mi][ni][3])
                        : "r"(a[mi][0]), "r"(a[mi][1]), "r"(a[mi][2]), "r"(a[mi][3]),
                          "r"(b[ni][0]), "r"(b[ni][1]));
        }
    };

    // prologue
    cpasync_A(0, 0);
    ldg_B(0);

#pragma unroll 1
    for (int t = 0; t < NTILES; ++t) {
        const int buf = t & 1;
        CP_WAIT0();                // A(t) resident
        store_B(buf);              // B(t) -> smem
        __syncthreads();           // stage t fully visible; prev compute done
        if (t + 1 < NTILES) {
            cpasync_A(t + 1, buf ^ 1);
            ldg_B(t + 1);
        }
        compute(buf);
    }

    // epilogue: add bias, write fp32
#pragma unroll
    for (int mi = 0; mi < 4; ++mi) {
        const int r0 = m_base + wm * 64 + mi * 16 + (lane >> 2);
#pragma unroll
        for (int ni = 0; ni < 4; ++ni) {
            const int col = n_base + wn * 32 + ni * 8 + (lane & 3) * 2;
            float2 bb = *reinterpret_cast<const float2*>(bias + col);
            float2 v0 = make_float2(acc[mi][ni][0] + bb.x, acc[mi][ni][1] + bb.y);
            float2 v1 = make_float2(acc[mi][ni][2] + bb.x, acc[mi][ni][3] + bb.y);
            *reinterpret_cast<float2*>(out + (size_t)r0 * N_TOT + col) = v0;
            *reinterpret_cast<float2*>(out + (size_t)(r0 + 8) * N_TOT + col) = v1;
        }
    }
}

// ---------------------------------------------------------------------------
// Launch
// ---------------------------------------------------------------------------
extern "C" void kernel_launch(void* const* d_in, const int* in_sizes, int n_in,
                              void* d_out, int out_size) {
    const float* x    = (const float*)d_in[0];
    const int*   q3   = (const int*)d_in[1];
    const void*  norm = (const void*)d_in[2];
    const float* bias = (const float*)d_in[3];
    float*       out  = (float*)d_out;

    // single fused pre-pass launch (repack + sniff + x->fp16)
    k_prep<<<NREPACK_BLOCKS + NCVT_BLOCKS, 256>>>(x, q3, norm);

    cudaFuncSetAttribute((const void*)k_gemm,
                         cudaFuncAttributeMaxDynamicSharedMemorySize, SMEM_BYTES);
    dim3 grid(N_TOT / BN, M_TOT / BM);   // 172 x 4 = 688 CTAs
    k_gemm<<<grid, NTHREADS, SMEM_BYTES>>>(bias, out);
}